// round 2
// baseline (speedup 1.0000x reference)
#include <cuda_runtime.h>
#include <cstdint>

// Problem constants
#define B_    4
#define HW_   4096
#define C_    256
#define D_    64

#define ROWS_PER_CTA 128      // query rows per CTA
#define THREADS      512      // 16 warps, 8 rows per warp
#define TJ           64       // K/V tile (j) size staged in smem

#define QS_STRIDE 68          // 64 + 4 pad (conflict-free float4 over d)
#define KS_STRIDE 68
#define VS_STRIDE 260         // 256 + 4 pad

#define SMEM_FLOATS (ROWS_PER_CTA*QS_STRIDE + TJ*KS_STRIDE + TJ*VS_STRIDE)
#define SMEM_BYTES  (SMEM_FLOATS * 4)

__device__ __forceinline__ float warp_max(float v) {
    #pragma unroll
    for (int o = 16; o > 0; o >>= 1) v = fmaxf(v, __shfl_xor_sync(0xffffffffu, v, o));
    return v;
}
__device__ __forceinline__ float warp_sum(float v) {
    #pragma unroll
    for (int o = 16; o > 0; o >>= 1) v += __shfl_xor_sync(0xffffffffu, v, o);
    return v;
}

__global__ void __launch_bounds__(THREADS, 1)
flash_attn_fp32_kernel(const float* __restrict__ g,
                       const float* __restrict__ x,
                       const float* __restrict__ xq,   // x_query  -> K
                       const float* __restrict__ pg,   // phi_g    -> Q
                       const float* __restrict__ xv,   // x_value  -> V
                       const float* __restrict__ kscal,
                       float* __restrict__ out)
{
    extern __shared__ float smem[];
    float* Qs = smem;                                   // [128][68]
    float* Ks = Qs + ROWS_PER_CTA * QS_STRIDE;          // [TJ][68]
    float* Vs = Ks + TJ * KS_STRIDE;                    // [TJ][260]

    const int b    = blockIdx.x >> 5;          // 32 row-blocks per batch
    const int rb   = blockIdx.x & 31;
    const int row0 = rb * ROWS_PER_CTA;

    const int tid  = threadIdx.x;
    const int warp = tid >> 5;
    const int lane = tid & 31;
    const int r0   = warp * 8;                 // first of this warp's 8 rows

    // ---- load Q block (phi_g rows) into smem ----
    for (int i = tid; i < ROWS_PER_CTA * D_; i += THREADS) {
        const int r = i >> 6, d = i & 63;
        Qs[r * QS_STRIDE + d] = pg[((size_t)b * HW_ + row0 + r) * D_ + d];
    }

    // ---- per-thread state ----
    float acc[64];                              // 8 rows x 8 cols (cols lane*8..lane*8+7)
    #pragma unroll
    for (int i = 0; i < 64; i++) acc[i] = 0.0f;
    float mrow[8], lrow[8];
    #pragma unroll
    for (int r = 0; r < 8; r++) { mrow[r] = -3.0e38f; lrow[r] = 0.0f; }

    __syncthreads();

    for (int jt = 0; jt < HW_; jt += TJ) {
        // stage K,V tile
        for (int i = tid; i < TJ * D_; i += THREADS) {
            const int j = i >> 6, d = i & 63;
            Ks[j * KS_STRIDE + d] = xq[((size_t)b * HW_ + jt + j) * D_ + d];
        }
        for (int i = tid; i < TJ * C_; i += THREADS) {
            const int j = i >> 8, c = i & 255;
            Vs[j * VS_STRIDE + c] = xv[((size_t)b * HW_ + jt + j) * C_ + c];
        }
        __syncthreads();

        #pragma unroll
        for (int jj = 0; jj < TJ; jj += 32) {
            // ---- logits: s[r] for j = jt + jj + lane ----
            float s[8];
            #pragma unroll
            for (int r = 0; r < 8; r++) s[r] = 0.0f;
            const float* kcol = &Ks[(jj + lane) * KS_STRIDE];
            #pragma unroll
            for (int d4 = 0; d4 < D_; d4 += 4) {
                const float4 kk = *(const float4*)(kcol + d4);
                #pragma unroll
                for (int r = 0; r < 8; r++) {
                    const float4 qq = *(const float4*)(&Qs[(r0 + r) * QS_STRIDE + d4]);
                    s[r] = fmaf(qq.x, kk.x, s[r]);
                    s[r] = fmaf(qq.y, kk.y, s[r]);
                    s[r] = fmaf(qq.z, kk.z, s[r]);
                    s[r] = fmaf(qq.w, kk.w, s[r]);
                }
            }

            // ---- online softmax update ----
            float p[8], scale[8];
            #pragma unroll
            for (int r = 0; r < 8; r++) {
                const float tm = warp_max(s[r]);
                const float nm = fmaxf(mrow[r], tm);
                scale[r] = __expf(mrow[r] - nm);
                p[r]     = __expf(s[r] - nm);
                mrow[r]  = nm;
            }
            #pragma unroll
            for (int r = 0; r < 8; r++) {
                const float ts = warp_sum(p[r]);
                lrow[r] = lrow[r] * scale[r] + ts;
            }
            #pragma unroll
            for (int r = 0; r < 8; r++) {
                #pragma unroll
                for (int c = 0; c < 8; c++) acc[r * 8 + c] *= scale[r];
            }

            // ---- accumulate O += P * V ----
            #pragma unroll 4
            for (int src = 0; src < 32; src++) {
                const float* vrow = &Vs[(jj + src) * VS_STRIDE + lane * 8];
                const float4 v0 = *(const float4*)(vrow);
                const float4 v1 = *(const float4*)(vrow + 4);
                #pragma unroll
                for (int r = 0; r < 8; r++) {
                    const float pb = __shfl_sync(0xffffffffu, p[r], src);
                    acc[r * 8 + 0] = fmaf(pb, v0.x, acc[r * 8 + 0]);
                    acc[r * 8 + 1] = fmaf(pb, v0.y, acc[r * 8 + 1]);
                    acc[r * 8 + 2] = fmaf(pb, v0.z, acc[r * 8 + 2]);
                    acc[r * 8 + 3] = fmaf(pb, v0.w, acc[r * 8 + 3]);
                    acc[r * 8 + 4] = fmaf(pb, v1.x, acc[r * 8 + 4]);
                    acc[r * 8 + 5] = fmaf(pb, v1.y, acc[r * 8 + 5]);
                    acc[r * 8 + 6] = fmaf(pb, v1.z, acc[r * 8 + 6]);
                    acc[r * 8 + 7] = fmaf(pb, v1.w, acc[r * 8 + 7]);
                }
            }
        }
        __syncthreads();   // protect Ks/Vs before next stage overwrites
    }

    // ---- epilogue: out[..,0:256] = k*SV + x ; out[..,256:512] = g ----
    const float kv = kscal[0];
    #pragma unroll
    for (int r = 0; r < 8; r++) {
        const int row = row0 + r0 + r;
        const float inv = 1.0f / lrow[r];
        const size_t obase = ((size_t)b * HW_ + row) * (2 * C_);
        const size_t ibase = ((size_t)b * HW_ + row) * C_;
        const int c0 = lane * 8;

        float4 o0, o1;
        const float4 x0 = *(const float4*)(&x[ibase + c0]);
        const float4 x1 = *(const float4*)(&x[ibase + c0 + 4]);
        o0.x = fmaf(kv, acc[r*8+0]*inv, x0.x);
        o0.y = fmaf(kv, acc[r*8+1]*inv, x0.y);
        o0.z = fmaf(kv, acc[r*8+2]*inv, x0.z);
        o0.w = fmaf(kv, acc[r*8+3]*inv, x0.w);
        o1.x = fmaf(kv, acc[r*8+4]*inv, x1.x);
        o1.y = fmaf(kv, acc[r*8+5]*inv, x1.y);
        o1.z = fmaf(kv, acc[r*8+6]*inv, x1.z);
        o1.w = fmaf(kv, acc[r*8+7]*inv, x1.w);
        *(float4*)(&out[obase + c0])     = o0;
        *(float4*)(&out[obase + c0 + 4]) = o1;

        const float4 g0 = *(const float4*)(&g[ibase + c0]);
        const float4 g1 = *(const float4*)(&g[ibase + c0 + 4]);
        *(float4*)(&out[obase + C_ + c0])     = g0;
        *(float4*)(&out[obase + C_ + c0 + 4]) = g1;
    }
}

extern "C" void kernel_launch(void* const* d_in, const int* in_sizes, int n_in,
                              void* d_out, int out_size)
{
    const float* g  = (const float*)d_in[0];
    const float* x  = (const float*)d_in[1];
    const float* xq = (const float*)d_in[2];
    const float* pg = (const float*)d_in[3];
    const float* xv = (const float*)d_in[4];
    const float* k  = (const float*)d_in[5];
    float* out = (float*)d_out;

    cudaFuncSetAttribute(flash_attn_fp32_kernel,
                         cudaFuncAttributeMaxDynamicSharedMemorySize, SMEM_BYTES);

    const int grid = (B_ * HW_) / ROWS_PER_CTA;   // 128
    flash_attn_fp32_kernel<<<grid, THREADS, SMEM_BYTES>>>(g, x, xq, pg, xv, k, out);
}